// round 7
// baseline (speedup 1.0000x reference)
#include <cuda_runtime.h>

#define NI      1022      // interior size (N-2)
#define NF      1024      // full size N
#define PITCH   1024      // padded row pitch (128B aligned)
#define BATCH   8
#define ROWS    8         // output rows per thread (step-0 kernel)
#define TY      4         // thread rows per block (step-0 kernel)
#define RROWS   12        // output rows per thread (fused rolling kernel)
#define FTY2    4         // thread.y per block (fused rolling kernel)

__device__ float g_bufA[BATCH * NI * PITCH];
__device__ float g_bufB[BATCH * NI * PITCH];
__device__ float g_force[BATCH * NI * PITCH];
__device__ float g_coef[9];
__device__ float g_cf[1];

__constant__ float c_coef[9];

// --- fold mu/k1/k2/k3 into 10 scalars ---------------------------------------
__global__ void setup_coef_kernel(const float* __restrict__ mu,
                                  const float* __restrict__ k1,
                                  const float* __restrict__ k2,
                                  const float* __restrict__ k3) {
    float s3 = 0.0f;
    #pragma unroll
    for (int i = 0; i < 9; i++) s3 += k3[i];
    float inv = 1.0f / s3;
    #pragma unroll
    for (int i = 0; i < 9; i++) g_coef[i] = (k1[i] + k2[i]) * inv;
    const float Hval = 1.0f / (float)(NF - 1);
    g_cf[0] = Hval * Hval / (mu[0] * s3);
}

// --- step 0 + force precompute fused -----------------------------------------
// Reads pre (compact pitch 1022) and f (NF x NF); computes
// force = f_interior * cf (stored to g_force for later passes) and
// out = force + conv(hard_encode(pre)) -> bufA (pitch 1024).
__global__ void __launch_bounds__(32 * TY)
step0_kernel(const float* __restrict__ pre,
             const float* __restrict__ f,
             float* __restrict__ out) {
    const unsigned FULL = 0xffffffffu;
    int lane  = threadIdx.x;
    int x0    = (blockIdx.x * 32 + lane) * 4;
    int ybase = (blockIdx.y * TY + threadIdx.y) * ROWS;
    int b     = blockIdx.z;

    float c0 = c_coef[0], c1 = c_coef[1], c2 = c_coef[2];
    float c3 = c_coef[3], c4 = c_coef[4], c5 = c_coef[5];
    float c6 = c_coef[6], c7 = c_coef[7], c8 = c_coef[8];
    const float cf = g_cf[0];

    const float* src = pre + (size_t)b * NI * NI;
    const bool L31 = (lane == 31);

    // acc init = force rows (computed from f), also persisted to g_force
    float4 acc[ROWS];
    #pragma unroll
    for (int i = 0; i < ROWS; i++) {
        int row = ybase + i;
        if (row < NI) {
            // force[row][x0..x0+3] = f[row+1][x0+1..x0+4] * cf
            const float* fp = f + ((size_t)b * NF + (row + 1)) * NF;
            float4 q = *(const float4*)(fp + x0);
            float t4 = __shfl_down_sync(FULL, q.x, 1);
            if (L31) t4 = (x0 + 4 < NF) ? fp[x0 + 4] : 0.0f;
            float4 a; a.x = q.y * cf; a.y = q.z * cf; a.z = q.w * cf; a.w = t4 * cf;
            acc[i] = a;
            float* frow = g_force + ((size_t)b * NI + row) * PITCH;
            if (x0 + 3 < NI) {
                *(float4*)(frow + x0) = a;
            } else {
                if (x0 + 0 < NI) frow[x0 + 0] = a.x;
                if (x0 + 1 < NI) frow[x0 + 1] = a.y;
                // padding cols must stay zero -> no store
            }
        } else {
            acc[i].x = acc[i].y = acc[i].z = acc[i].w = 0.0f;
        }
    }

    #pragma unroll
    for (int rj = 0; rj <= ROWS + 1; rj++) {
        int ri  = rj - 1;
        int row = ybase + ri;
        if (row < 0 || row >= NI) continue;

        const float* rp = src + (size_t)row * NI;
        float l, rr; float4 v;
        l   = (x0 - 1 >= 0 && x0 - 1 < NI) ? rp[x0 - 1] : 0.0f;
        v.x = (x0 + 0 < NI) ? rp[x0 + 0] : 0.0f;
        v.y = (x0 + 1 < NI) ? rp[x0 + 1] : 0.0f;
        v.z = (x0 + 2 < NI) ? rp[x0 + 2] : 0.0f;
        v.w = (x0 + 3 < NI) ? rp[x0 + 3] : 0.0f;
        rr  = (x0 + 4 < NI) ? rp[x0 + 4] : 0.0f;

        if (ri + 1 >= 0 && ri + 1 < ROWS) {
            acc[ri + 1].x += c0 * l   + c1 * v.x + c2 * v.y;
            acc[ri + 1].y += c0 * v.x + c1 * v.y + c2 * v.z;
            acc[ri + 1].z += c0 * v.y + c1 * v.z + c2 * v.w;
            acc[ri + 1].w += c0 * v.z + c1 * v.w + c2 * rr;
        }
        if (ri >= 0 && ri < ROWS) {
            acc[ri].x += c3 * l   + c4 * v.x + c5 * v.y;
            acc[ri].y += c3 * v.x + c4 * v.y + c5 * v.z;
            acc[ri].z += c3 * v.y + c4 * v.z + c5 * v.w;
            acc[ri].w += c3 * v.z + c4 * v.w + c5 * rr;
        }
        if (ri - 1 >= 0 && ri - 1 < ROWS) {
            acc[ri - 1].x += c6 * l   + c7 * v.x + c8 * v.y;
            acc[ri - 1].y += c6 * v.x + c7 * v.y + c8 * v.z;
            acc[ri - 1].z += c6 * v.y + c7 * v.z + c8 * v.w;
            acc[ri - 1].w += c6 * v.z + c7 * v.w + c8 * rr;
        }
    }

    #pragma unroll
    for (int i = 0; i < ROWS; i++) {
        int row = ybase + i;
        if (row >= NI) continue;
        float* orow = out + ((size_t)b * NI + row) * PITCH;
        if (x0 + 3 < NI) {
            *(float4*)(orow + x0) = acc[i];
        } else {
            if (x0 + 0 < NI) orow[x0 + 0] = acc[i].x;
            if (x0 + 1 < NI) orow[x0 + 1] = acc[i].y;
        }
    }
}

// --- fused 2-step Jacobi, register-rolling, smem-free ------------------------
// Thread owns cols [x0, x0+4) and output rows [ybase, ybase+RROWS).
// Rolling over input rows r: mid row r-1 (6-wide, cols x0-1..x0+4) from input
// rows r-2..r (8-wide via shfl), output row r-2 (4-wide) from mid rows r-3..r-1.
// Input must be pitch-1024 with zero padding cols (g_bufA/g_bufB invariant).
template<bool COMPACT_OUT>
__global__ void __launch_bounds__(32 * FTY2, 8)
fused2r_kernel(const float* __restrict__ in,
               float* __restrict__ out, int out_pitch) {
    const unsigned FULL = 0xffffffffu;
    const int lane  = threadIdx.x;
    const int x0    = (blockIdx.x * 32 + lane) * 4;
    const int ybase = (blockIdx.y * FTY2 + threadIdx.y) * RROWS;
    const int b     = blockIdx.z;

    const float c0 = c_coef[0], c1 = c_coef[1], c2 = c_coef[2];
    const float c3 = c_coef[3], c4 = c_coef[4], c5 = c_coef[5];
    const float c6 = c_coef[6], c7 = c_coef[7], c8 = c_coef[8];

    const float* src = in      + (size_t)b * NI * PITCH;
    const float* frc = g_force + (size_t)b * NI * PITCH;
    float*       dst = out     + (size_t)b * NI * out_pitch;

    const bool L0  = (lane == 0);
    const bool L31 = (lane == 31);

    float inA[8], inB[8], inC[8];   // input rows r-2, r-1, r (cols x0-2..x0+5)
    float mA[6],  mB[6],  mC[6];    // mid rows r-3, r-2, r-1 (cols x0-1..x0+4)
    float4 fA, fB;                  // force rows r-2, r-1

    #pragma unroll
    for (int i = 0; i < 8; i++) { inA[i] = 0.f; inB[i] = 0.f; inC[i] = 0.f; }
    #pragma unroll
    for (int i = 0; i < 6; i++) { mA[i] = 0.f; mB[i] = 0.f; mC[i] = 0.f; }
    fA.x = fA.y = fA.z = fA.w = 0.f;
    fB = fA;

    #pragma unroll 4
    for (int it = 0; it < RROWS + 4; it++) {
        const int r = ybase - 2 + it;

        // ---- shift input window, load row r ----
        #pragma unroll
        for (int i = 0; i < 8; i++) { inA[i] = inB[i]; inB[i] = inC[i]; }
        {
            float4 v; v.x = v.y = v.z = v.w = 0.f;
            float l2 = 0.f, l1 = 0.f, r4 = 0.f, r5 = 0.f;
            if ((unsigned)r < (unsigned)NI) {
                const float* rp = src + (size_t)r * PITCH;
                v = *(const float4*)(rp + x0);
                if (L0) {
                    l2 = (x0 >= 2) ? rp[x0 - 2] : 0.f;
                    l1 = (x0 >= 1) ? rp[x0 - 1] : 0.f;
                }
                if (L31) {
                    r4 = (x0 + 4 < NI) ? rp[x0 + 4] : 0.f;
                    r5 = (x0 + 5 < NI) ? rp[x0 + 5] : 0.f;
                }
            }
            float sl2 = __shfl_up_sync(FULL, v.z, 1);
            float sl1 = __shfl_up_sync(FULL, v.w, 1);
            float sr4 = __shfl_down_sync(FULL, v.x, 1);
            float sr5 = __shfl_down_sync(FULL, v.y, 1);
            if (!L0)  { l2 = sl2; l1 = sl1; }
            if (!L31) { r4 = sr4; r5 = sr5; }
            inC[0] = l2;  inC[1] = l1;
            inC[2] = v.x; inC[3] = v.y; inC[4] = v.z; inC[5] = v.w;
            inC[6] = r4;  inC[7] = r5;
        }

        // ---- shift mid window + force, compute mid row rm = r-1 ----
        #pragma unroll
        for (int i = 0; i < 6; i++) { mA[i] = mB[i]; mB[i] = mC[i]; }
        fA = fB;

        const int rm = r - 1;
        {
            float4 f4; f4.x = f4.y = f4.z = f4.w = 0.f;
            float fl = 0.f, fr = 0.f;
            const bool rowok = ((unsigned)rm < (unsigned)NI);
            if (rowok) {
                const float* fp = frc + (size_t)rm * PITCH;
                f4 = *(const float4*)(fp + x0);
                if (L0)  fl = (x0 >= 1)     ? fp[x0 - 1] : 0.f;
                if (L31) fr = (x0 + 4 < NI) ? fp[x0 + 4] : 0.f;
            }
            float sfl = __shfl_up_sync(FULL, f4.w, 1);
            float sfr = __shfl_down_sync(FULL, f4.x, 1);
            if (!L0)  fl = sfl;
            if (!L31) fr = sfr;
            fB = f4;

            if (rowok) {
                float f6[6];
                f6[0] = fl;   f6[1] = f4.x; f6[2] = f4.y;
                f6[3] = f4.z; f6[4] = f4.w; f6[5] = fr;
                #pragma unroll
                for (int i = 0; i < 6; i++) {
                    int gc = x0 - 1 + i;
                    float vmid = f6[i]
                        + c0 * inA[i] + c1 * inA[i + 1] + c2 * inA[i + 2]
                        + c3 * inB[i] + c4 * inB[i + 1] + c5 * inB[i + 2]
                        + c6 * inC[i] + c7 * inC[i + 1] + c8 * inC[i + 2];
                    mC[i] = ((unsigned)gc < (unsigned)NI) ? vmid : 0.f;
                }
            } else {
                #pragma unroll
                for (int i = 0; i < 6; i++) mC[i] = 0.f;
            }
        }

        // ---- output row ro = r-2 ----
        const int ro = r - 2;
        if (ro >= ybase && ro < NI) {
            float o[4];
            #pragma unroll
            for (int j = 0; j < 4; j++) {
                o[j] = c0 * mA[j] + c1 * mA[j + 1] + c2 * mA[j + 2]
                     + c3 * mB[j] + c4 * mB[j + 1] + c5 * mB[j + 2]
                     + c6 * mC[j] + c7 * mC[j + 1] + c8 * mC[j + 2];
            }
            float* orow = dst + (size_t)ro * out_pitch;
            if (!COMPACT_OUT && x0 + 3 < NI) {
                float4 ov;
                ov.x = o[0] + fA.x; ov.y = o[1] + fA.y;
                ov.z = o[2] + fA.z; ov.w = o[3] + fA.w;
                *(float4*)(orow + x0) = ov;
            } else {
                if (x0 + 0 < NI) orow[x0 + 0] = o[0] + fA.x;
                if (x0 + 1 < NI) orow[x0 + 1] = o[1] + fA.y;
                if (x0 + 2 < NI) orow[x0 + 2] = o[2] + fA.z;
                if (x0 + 3 < NI) orow[x0 + 3] = o[3] + fA.w;
            }
        }
    }
}

extern "C" void kernel_launch(void* const* d_in, const int* in_sizes, int n_in,
                              void* d_out, int out_size) {
    // metadata order: x, pre, f, mu, k1, k2, k3  (x unused by the reference)
    const float* pre = (const float*)d_in[1];
    const float* f   = (const float*)d_in[2];
    const float* mu  = (const float*)d_in[3];
    const float* k1  = (const float*)d_in[4];
    const float* k2  = (const float*)d_in[5];
    const float* k3  = (const float*)d_in[6];
    float* out = (float*)d_out;

    void *pA = nullptr, *pB = nullptr, *pC = nullptr;
    cudaGetSymbolAddress(&pA, g_bufA);
    cudaGetSymbolAddress(&pB, g_bufB);
    cudaGetSymbolAddress(&pC, g_coef);

    setup_coef_kernel<<<1, 1>>>(mu, k1, k2, k3);
    cudaMemcpyToSymbolAsync(c_coef, pC, 9 * sizeof(float), 0,
                            cudaMemcpyDeviceToDevice);

    // step 0 (single) + force precompute, fused: pre,f -> bufA, g_force
    {
        dim3 blk(32, TY, 1);
        dim3 grd(NF / 128, (NI + TY * ROWS - 1) / (TY * ROWS), BATCH);
        step0_kernel<<<grd, blk>>>(pre, f, (float*)pA);
    }

    // 5 fused double-steps: steps 1..10
    dim3 fblk(32, FTY2, 1);
    dim3 fgrd(NF / 128, (NI + FTY2 * RROWS - 1) / (FTY2 * RROWS), BATCH);

    fused2r_kernel<false><<<fgrd, fblk>>>((const float*)pA, (float*)pB, PITCH);
    fused2r_kernel<false><<<fgrd, fblk>>>((const float*)pB, (float*)pA, PITCH);
    fused2r_kernel<false><<<fgrd, fblk>>>((const float*)pA, (float*)pB, PITCH);
    fused2r_kernel<false><<<fgrd, fblk>>>((const float*)pB, (float*)pA, PITCH);
    fused2r_kernel<true ><<<fgrd, fblk>>>((const float*)pA, out, NI);
}

// round 8
// speedup vs baseline: 1.2012x; 1.2012x over previous
#include <cuda_runtime.h>

#define NI      1022      // interior size (N-2)
#define NF      1024      // full size N
#define PITCH   1024      // padded row pitch (128B aligned)
#define BATCH   8
#define ROWS    8         // output rows per thread (step-0 kernel)
#define TY      4         // thread rows per block (step-0 kernel)
#define RROWS   20        // output rows per thread (fused rolling kernel)
#define FTY2    4         // thread.y per block (fused rolling kernel)

__device__ float g_bufA[BATCH * NI * PITCH];
__device__ float g_bufB[BATCH * NI * PITCH];
__device__ float g_force[BATCH * NI * PITCH];
__device__ float g_coef[9];
__device__ float g_cf[1];

__constant__ float c_coef[9];

// --- fold mu/k1/k2/k3 into 10 scalars ---------------------------------------
__global__ void setup_coef_kernel(const float* __restrict__ mu,
                                  const float* __restrict__ k1,
                                  const float* __restrict__ k2,
                                  const float* __restrict__ k3) {
    float s3 = 0.0f;
    #pragma unroll
    for (int i = 0; i < 9; i++) s3 += k3[i];
    float inv = 1.0f / s3;
    #pragma unroll
    for (int i = 0; i < 9; i++) g_coef[i] = (k1[i] + k2[i]) * inv;
    const float Hval = 1.0f / (float)(NF - 1);
    g_cf[0] = Hval * Hval / (mu[0] * s3);
}

// --- step 0 + force precompute fused -----------------------------------------
__global__ void __launch_bounds__(32 * TY)
step0_kernel(const float* __restrict__ pre,
             const float* __restrict__ f,
             float* __restrict__ out) {
    const unsigned FULL = 0xffffffffu;
    int lane  = threadIdx.x;
    int x0    = (blockIdx.x * 32 + lane) * 4;
    int ybase = (blockIdx.y * TY + threadIdx.y) * ROWS;
    int b     = blockIdx.z;

    float c0 = c_coef[0], c1 = c_coef[1], c2 = c_coef[2];
    float c3 = c_coef[3], c4 = c_coef[4], c5 = c_coef[5];
    float c6 = c_coef[6], c7 = c_coef[7], c8 = c_coef[8];
    const float cf = g_cf[0];

    const float* src = pre + (size_t)b * NI * NI;
    const bool L31 = (lane == 31);

    float4 acc[ROWS];
    #pragma unroll
    for (int i = 0; i < ROWS; i++) {
        int row = ybase + i;
        if (row < NI) {
            const float* fp = f + ((size_t)b * NF + (row + 1)) * NF;
            float4 q = *(const float4*)(fp + x0);
            float t4 = __shfl_down_sync(FULL, q.x, 1);
            if (L31) t4 = (x0 + 4 < NF) ? fp[x0 + 4] : 0.0f;
            float4 a; a.x = q.y * cf; a.y = q.z * cf; a.z = q.w * cf; a.w = t4 * cf;
            acc[i] = a;
            float* frow = g_force + ((size_t)b * NI + row) * PITCH;
            if (x0 + 3 < NI) {
                *(float4*)(frow + x0) = a;
            } else {
                if (x0 + 0 < NI) frow[x0 + 0] = a.x;
                if (x0 + 1 < NI) frow[x0 + 1] = a.y;
            }
        } else {
            acc[i].x = acc[i].y = acc[i].z = acc[i].w = 0.0f;
        }
    }

    #pragma unroll
    for (int rj = 0; rj <= ROWS + 1; rj++) {
        int ri  = rj - 1;
        int row = ybase + ri;
        if (row < 0 || row >= NI) continue;

        const float* rp = src + (size_t)row * NI;
        float l, rr; float4 v;
        l   = (x0 - 1 >= 0 && x0 - 1 < NI) ? rp[x0 - 1] : 0.0f;
        v.x = (x0 + 0 < NI) ? rp[x0 + 0] : 0.0f;
        v.y = (x0 + 1 < NI) ? rp[x0 + 1] : 0.0f;
        v.z = (x0 + 2 < NI) ? rp[x0 + 2] : 0.0f;
        v.w = (x0 + 3 < NI) ? rp[x0 + 3] : 0.0f;
        rr  = (x0 + 4 < NI) ? rp[x0 + 4] : 0.0f;

        if (ri + 1 >= 0 && ri + 1 < ROWS) {
            acc[ri + 1].x += c0 * l   + c1 * v.x + c2 * v.y;
            acc[ri + 1].y += c0 * v.x + c1 * v.y + c2 * v.z;
            acc[ri + 1].z += c0 * v.y + c1 * v.z + c2 * v.w;
            acc[ri + 1].w += c0 * v.z + c1 * v.w + c2 * rr;
        }
        if (ri >= 0 && ri < ROWS) {
            acc[ri].x += c3 * l   + c4 * v.x + c5 * v.y;
            acc[ri].y += c3 * v.x + c4 * v.y + c5 * v.z;
            acc[ri].z += c3 * v.y + c4 * v.z + c5 * v.w;
            acc[ri].w += c3 * v.z + c4 * v.w + c5 * rr;
        }
        if (ri - 1 >= 0 && ri - 1 < ROWS) {
            acc[ri - 1].x += c6 * l   + c7 * v.x + c8 * v.y;
            acc[ri - 1].y += c6 * v.x + c7 * v.y + c8 * v.z;
            acc[ri - 1].z += c6 * v.y + c7 * v.z + c8 * v.w;
            acc[ri - 1].w += c6 * v.z + c7 * v.w + c8 * rr;
        }
    }

    #pragma unroll
    for (int i = 0; i < ROWS; i++) {
        int row = ybase + i;
        if (row >= NI) continue;
        float* orow = out + ((size_t)b * NI + row) * PITCH;
        if (x0 + 3 < NI) {
            *(float4*)(orow + x0) = acc[i];
        } else {
            if (x0 + 0 < NI) orow[x0 + 0] = acc[i].x;
            if (x0 + 1 < NI) orow[x0 + 1] = acc[i].y;
        }
    }
}

// --- prefetch helpers ---------------------------------------------------------
__device__ __forceinline__ void issue_src(const float* __restrict__ src, int r,
                                          int x0, bool L0, bool L31,
                                          float4& v, float& l2, float& l1,
                                          float& r4, float& r5) {
    v.x = v.y = v.z = v.w = 0.f;
    l2 = l1 = r4 = r5 = 0.f;
    if ((unsigned)r < (unsigned)NI) {
        const float* rp = src + (size_t)r * PITCH;
        v = *(const float4*)(rp + x0);
        if (L0) {
            l2 = (x0 >= 2) ? rp[x0 - 2] : 0.f;
            l1 = (x0 >= 1) ? rp[x0 - 1] : 0.f;
        }
        if (L31) {
            r4 = (x0 + 4 < NI) ? rp[x0 + 4] : 0.f;
            r5 = (x0 + 5 < NI) ? rp[x0 + 5] : 0.f;
        }
    }
}

__device__ __forceinline__ void issue_frc(const float* __restrict__ frc, int r,
                                          int x0, bool L0, bool L31,
                                          float4& f4, float& fl, float& fr) {
    f4.x = f4.y = f4.z = f4.w = 0.f;
    fl = fr = 0.f;
    if ((unsigned)r < (unsigned)NI) {
        const float* fp = frc + (size_t)r * PITCH;
        f4 = *(const float4*)(fp + x0);
        if (L0)  fl = (x0 >= 1)     ? fp[x0 - 1] : 0.f;
        if (L31) fr = (x0 + 4 < NI) ? fp[x0 + 4] : 0.f;
    }
}

// --- fused 2-step Jacobi, register-rolling, prefetched ------------------------
template<bool COMPACT_OUT>
__global__ void __launch_bounds__(32 * FTY2)
fused2r_kernel(const float* __restrict__ in,
               float* __restrict__ out, int out_pitch) {
    const unsigned FULL = 0xffffffffu;
    const int lane  = threadIdx.x;
    const int x0    = (blockIdx.x * 32 + lane) * 4;
    const int ybase = (blockIdx.y * FTY2 + threadIdx.y) * RROWS;
    const int b     = blockIdx.z;

    const float c0 = c_coef[0], c1 = c_coef[1], c2 = c_coef[2];
    const float c3 = c_coef[3], c4 = c_coef[4], c5 = c_coef[5];
    const float c6 = c_coef[6], c7 = c_coef[7], c8 = c_coef[8];

    const float* src = in      + (size_t)b * NI * PITCH;
    const float* frc = g_force + (size_t)b * NI * PITCH;
    float*       dst = out     + (size_t)b * NI * out_pitch;

    const bool L0  = (lane == 0);
    const bool L31 = (lane == 31);

    float inA[8], inB[8], inC[8];   // input rows r-2, r-1, r (cols x0-2..x0+5)
    float mA[6],  mB[6],  mC[6];    // mid rows r-3, r-2, r-1 (cols x0-1..x0+4)
    float4 fA, fB;                  // force rows r-2, r-1 (4-wide kept)

    #pragma unroll
    for (int i = 0; i < 8; i++) { inA[i] = 0.f; inB[i] = 0.f; inC[i] = 0.f; }
    #pragma unroll
    for (int i = 0; i < 6; i++) { mA[i] = 0.f; mB[i] = 0.f; mC[i] = 0.f; }
    fA.x = fA.y = fA.z = fA.w = 0.f;
    fB = fA;

    // prefetch registers for iteration 0: src row ybase-2, force row ybase-3
    float4 pv;  float pl2, pl1, pr4, pr5;
    float4 pf;  float pfl, pfr;
    issue_src(src, ybase - 2, x0, L0, L31, pv, pl2, pl1, pr4, pr5);
    issue_frc(frc, ybase - 3, x0, L0, L31, pf, pfl, pfr);

    for (int it = 0; it < RROWS + 4; it++) {
        const int r = ybase - 2 + it;

        // consume prefetched values
        float4 cv = pv;  float cl2 = pl2, cl1 = pl1, cr4 = pr4, cr5 = pr5;
        float4 cf4 = pf; float cfl = pfl, cfr = pfr;

        // issue next iteration's loads NOW (overlap with compute below)
        issue_src(src, r + 1, x0, L0, L31, pv, pl2, pl1, pr4, pr5);
        issue_frc(frc, r,     x0, L0, L31, pf, pfl, pfr);

        // ---- shift input window, assemble row r ----
        #pragma unroll
        for (int i = 0; i < 8; i++) { inA[i] = inB[i]; inB[i] = inC[i]; }
        {
            float sl2 = __shfl_up_sync(FULL, cv.z, 1);
            float sl1 = __shfl_up_sync(FULL, cv.w, 1);
            float sr4 = __shfl_down_sync(FULL, cv.x, 1);
            float sr5 = __shfl_down_sync(FULL, cv.y, 1);
            float l2 = L0 ? cl2 : sl2;
            float l1 = L0 ? cl1 : sl1;
            float r4 = L31 ? cr4 : sr4;
            float r5 = L31 ? cr5 : sr5;
            inC[0] = l2;   inC[1] = l1;
            inC[2] = cv.x; inC[3] = cv.y; inC[4] = cv.z; inC[5] = cv.w;
            inC[6] = r4;   inC[7] = r5;
        }

        // ---- shift mid window + force, compute mid row rm = r-1 ----
        #pragma unroll
        for (int i = 0; i < 6; i++) { mA[i] = mB[i]; mB[i] = mC[i]; }
        fA = fB;

        const int rm = r - 1;
        {
            float sfl = __shfl_up_sync(FULL, cf4.w, 1);
            float sfr = __shfl_down_sync(FULL, cf4.x, 1);
            float fl = L0 ? cfl : sfl;
            float fr = L31 ? cfr : sfr;
            fB = cf4;

            if ((unsigned)rm < (unsigned)NI) {
                float f6[6];
                f6[0] = fl;    f6[1] = cf4.x; f6[2] = cf4.y;
                f6[3] = cf4.z; f6[4] = cf4.w; f6[5] = fr;
                #pragma unroll
                for (int i = 0; i < 6; i++) {
                    int gc = x0 - 1 + i;
                    float vmid = f6[i]
                        + c0 * inA[i] + c1 * inA[i + 1] + c2 * inA[i + 2]
                        + c3 * inB[i] + c4 * inB[i + 1] + c5 * inB[i + 2]
                        + c6 * inC[i] + c7 * inC[i + 1] + c8 * inC[i + 2];
                    mC[i] = ((unsigned)gc < (unsigned)NI) ? vmid : 0.f;
                }
            } else {
                #pragma unroll
                for (int i = 0; i < 6; i++) mC[i] = 0.f;
            }
        }

        // ---- output row ro = r-2 ----
        const int ro = r - 2;
        if (ro >= ybase && ro < NI) {
            float o[4];
            #pragma unroll
            for (int j = 0; j < 4; j++) {
                o[j] = c0 * mA[j] + c1 * mA[j + 1] + c2 * mA[j + 2]
                     + c3 * mB[j] + c4 * mB[j + 1] + c5 * mB[j + 2]
                     + c6 * mC[j] + c7 * mC[j + 1] + c8 * mC[j + 2];
            }
            float* orow = dst + (size_t)ro * out_pitch;
            if (!COMPACT_OUT && x0 + 3 < NI) {
                float4 ov;
                ov.x = o[0] + fA.x; ov.y = o[1] + fA.y;
                ov.z = o[2] + fA.z; ov.w = o[3] + fA.w;
                *(float4*)(orow + x0) = ov;
            } else {
                if (x0 + 0 < NI) orow[x0 + 0] = o[0] + fA.x;
                if (x0 + 1 < NI) orow[x0 + 1] = o[1] + fA.y;
                if (x0 + 2 < NI) orow[x0 + 2] = o[2] + fA.z;
                if (x0 + 3 < NI) orow[x0 + 3] = o[3] + fA.w;
            }
        }
    }
}

extern "C" void kernel_launch(void* const* d_in, const int* in_sizes, int n_in,
                              void* d_out, int out_size) {
    // metadata order: x, pre, f, mu, k1, k2, k3  (x unused by the reference)
    const float* pre = (const float*)d_in[1];
    const float* f   = (const float*)d_in[2];
    const float* mu  = (const float*)d_in[3];
    const float* k1  = (const float*)d_in[4];
    const float* k2  = (const float*)d_in[5];
    const float* k3  = (const float*)d_in[6];
    float* out = (float*)d_out;

    void *pA = nullptr, *pB = nullptr, *pC = nullptr;
    cudaGetSymbolAddress(&pA, g_bufA);
    cudaGetSymbolAddress(&pB, g_bufB);
    cudaGetSymbolAddress(&pC, g_coef);

    setup_coef_kernel<<<1, 1>>>(mu, k1, k2, k3);
    cudaMemcpyToSymbolAsync(c_coef, pC, 9 * sizeof(float), 0,
                            cudaMemcpyDeviceToDevice);

    // step 0 (single) + force precompute, fused: pre,f -> bufA, g_force
    {
        dim3 blk(32, TY, 1);
        dim3 grd(NF / 128, (NI + TY * ROWS - 1) / (TY * ROWS), BATCH);
        step0_kernel<<<grd, blk>>>(pre, f, (float*)pA);
    }

    // 5 fused double-steps: steps 1..10
    dim3 fblk(32, FTY2, 1);
    dim3 fgrd(NF / 128, (NI + FTY2 * RROWS - 1) / (FTY2 * RROWS), BATCH);

    fused2r_kernel<false><<<fgrd, fblk>>>((const float*)pA, (float*)pB, PITCH);
    fused2r_kernel<false><<<fgrd, fblk>>>((const float*)pB, (float*)pA, PITCH);
    fused2r_kernel<false><<<fgrd, fblk>>>((const float*)pA, (float*)pB, PITCH);
    fused2r_kernel<false><<<fgrd, fblk>>>((const float*)pB, (float*)pA, PITCH);
    fused2r_kernel<true ><<<fgrd, fblk>>>((const float*)pA, out, NI);
}

// round 9
// speedup vs baseline: 1.2511x; 1.0416x over previous
#include <cuda_runtime.h>

#define NI      1022      // interior size (N-2)
#define NF      1024      // full size N
#define PITCH   1024      // padded row pitch (128B aligned)
#define BATCH   8
#define ROWS    8         // output rows per thread (step-0 kernel)
#define TY      4         // thread rows per block (step-0 kernel)
#define RROWS   8         // output rows per thread (fused rolling kernel)
#define FTY2    4         // thread.y per block (fused rolling kernel)

__device__ float g_bufA[BATCH * NI * PITCH];
__device__ float g_bufB[BATCH * NI * PITCH];
__device__ float g_force[BATCH * NI * PITCH];
__device__ float g_coef[9];
__device__ float g_cf[1];

__constant__ float c_coef[9];

// --- fold mu/k1/k2/k3 into 10 scalars ---------------------------------------
__global__ void setup_coef_kernel(const float* __restrict__ mu,
                                  const float* __restrict__ k1,
                                  const float* __restrict__ k2,
                                  const float* __restrict__ k3) {
    float s3 = 0.0f;
    #pragma unroll
    for (int i = 0; i < 9; i++) s3 += k3[i];
    float inv = 1.0f / s3;
    #pragma unroll
    for (int i = 0; i < 9; i++) g_coef[i] = (k1[i] + k2[i]) * inv;
    const float Hval = 1.0f / (float)(NF - 1);
    g_cf[0] = Hval * Hval / (mu[0] * s3);
}

// --- step 0 + force precompute fused -----------------------------------------
// Reads pre (compact pitch 1022) and f (NF x NF); computes
// force = f_interior * cf (stored to g_force) and
// out = force + conv(hard_encode(pre)) -> bufA (pitch 1024).
__global__ void __launch_bounds__(32 * TY)
step0_kernel(const float* __restrict__ pre,
             const float* __restrict__ f,
             float* __restrict__ out) {
    const unsigned FULL = 0xffffffffu;
    int lane  = threadIdx.x;
    int x0    = (blockIdx.x * 32 + lane) * 4;
    int ybase = (blockIdx.y * TY + threadIdx.y) * ROWS;
    int b     = blockIdx.z;

    float c0 = c_coef[0], c1 = c_coef[1], c2 = c_coef[2];
    float c3 = c_coef[3], c4 = c_coef[4], c5 = c_coef[5];
    float c6 = c_coef[6], c7 = c_coef[7], c8 = c_coef[8];
    const float cf = g_cf[0];

    const float* src = pre + (size_t)b * NI * NI;
    const bool L31 = (lane == 31);

    float4 acc[ROWS];
    #pragma unroll
    for (int i = 0; i < ROWS; i++) {
        int row = ybase + i;
        if (row < NI) {
            const float* fp = f + ((size_t)b * NF + (row + 1)) * NF;
            float4 q = *(const float4*)(fp + x0);
            float t4 = __shfl_down_sync(FULL, q.x, 1);
            if (L31) t4 = (x0 + 4 < NF) ? fp[x0 + 4] : 0.0f;
            float4 a; a.x = q.y * cf; a.y = q.z * cf; a.z = q.w * cf; a.w = t4 * cf;
            acc[i] = a;
            float* frow = g_force + ((size_t)b * NI + row) * PITCH;
            if (x0 + 3 < NI) {
                *(float4*)(frow + x0) = a;
            } else {
                if (x0 + 0 < NI) frow[x0 + 0] = a.x;
                if (x0 + 1 < NI) frow[x0 + 1] = a.y;
            }
        } else {
            acc[i].x = acc[i].y = acc[i].z = acc[i].w = 0.0f;
        }
    }

    #pragma unroll
    for (int rj = 0; rj <= ROWS + 1; rj++) {
        int ri  = rj - 1;
        int row = ybase + ri;
        if (row < 0 || row >= NI) continue;

        const float* rp = src + (size_t)row * NI;
        float l, rr; float4 v;
        l   = (x0 - 1 >= 0 && x0 - 1 < NI) ? rp[x0 - 1] : 0.0f;
        v.x = (x0 + 0 < NI) ? rp[x0 + 0] : 0.0f;
        v.y = (x0 + 1 < NI) ? rp[x0 + 1] : 0.0f;
        v.z = (x0 + 2 < NI) ? rp[x0 + 2] : 0.0f;
        v.w = (x0 + 3 < NI) ? rp[x0 + 3] : 0.0f;
        rr  = (x0 + 4 < NI) ? rp[x0 + 4] : 0.0f;

        if (ri + 1 >= 0 && ri + 1 < ROWS) {
            acc[ri + 1].x += c0 * l   + c1 * v.x + c2 * v.y;
            acc[ri + 1].y += c0 * v.x + c1 * v.y + c2 * v.z;
            acc[ri + 1].z += c0 * v.y + c1 * v.z + c2 * v.w;
            acc[ri + 1].w += c0 * v.z + c1 * v.w + c2 * rr;
        }
        if (ri >= 0 && ri < ROWS) {
            acc[ri].x += c3 * l   + c4 * v.x + c5 * v.y;
            acc[ri].y += c3 * v.x + c4 * v.y + c5 * v.z;
            acc[ri].z += c3 * v.y + c4 * v.z + c5 * v.w;
            acc[ri].w += c3 * v.z + c4 * v.w + c5 * rr;
        }
        if (ri - 1 >= 0 && ri - 1 < ROWS) {
            acc[ri - 1].x += c6 * l   + c7 * v.x + c8 * v.y;
            acc[ri - 1].y += c6 * v.x + c7 * v.y + c8 * v.z;
            acc[ri - 1].z += c6 * v.y + c7 * v.z + c8 * v.w;
            acc[ri - 1].w += c6 * v.z + c7 * v.w + c8 * rr;
        }
    }

    #pragma unroll
    for (int i = 0; i < ROWS; i++) {
        int row = ybase + i;
        if (row >= NI) continue;
        float* orow = out + ((size_t)b * NI + row) * PITCH;
        if (x0 + 3 < NI) {
            *(float4*)(orow + x0) = acc[i];
        } else {
            if (x0 + 0 < NI) orow[x0 + 0] = acc[i].x;
            if (x0 + 1 < NI) orow[x0 + 1] = acc[i].y;
        }
    }
}

// --- fused 2-step Jacobi, register-rolling, smem-free (R6 body) --------------
// Thread owns cols [x0, x0+4) and output rows [ybase, ybase+RROWS).
template<bool COMPACT_OUT>
__global__ void __launch_bounds__(32 * FTY2)
fused2r_kernel(const float* __restrict__ in,
               float* __restrict__ out, int out_pitch) {
    const unsigned FULL = 0xffffffffu;
    const int lane  = threadIdx.x;
    const int x0    = (blockIdx.x * 32 + lane) * 4;
    const int ybase = (blockIdx.y * FTY2 + threadIdx.y) * RROWS;
    const int b     = blockIdx.z;

    const float c0 = c_coef[0], c1 = c_coef[1], c2 = c_coef[2];
    const float c3 = c_coef[3], c4 = c_coef[4], c5 = c_coef[5];
    const float c6 = c_coef[6], c7 = c_coef[7], c8 = c_coef[8];

    const float* src = in      + (size_t)b * NI * PITCH;
    const float* frc = g_force + (size_t)b * NI * PITCH;
    float*       dst = out     + (size_t)b * NI * out_pitch;

    const bool L0  = (lane == 0);
    const bool L31 = (lane == 31);

    float inA[8], inB[8], inC[8];   // input rows r-2, r-1, r (cols x0-2..x0+5)
    float mA[6],  mB[6],  mC[6];    // mid rows r-3, r-2, r-1 (cols x0-1..x0+4)
    float4 fA, fB;                  // force rows r-2, r-1

    #pragma unroll
    for (int i = 0; i < 8; i++) { inA[i] = 0.f; inB[i] = 0.f; inC[i] = 0.f; }
    #pragma unroll
    for (int i = 0; i < 6; i++) { mA[i] = 0.f; mB[i] = 0.f; mC[i] = 0.f; }
    fA.x = fA.y = fA.z = fA.w = 0.f;
    fB = fA;

    for (int it = 0; it < RROWS + 4; it++) {
        const int r = ybase - 2 + it;

        // ---- shift input window, load row r ----
        #pragma unroll
        for (int i = 0; i < 8; i++) { inA[i] = inB[i]; inB[i] = inC[i]; }
        {
            float4 v; v.x = v.y = v.z = v.w = 0.f;
            float l2 = 0.f, l1 = 0.f, r4 = 0.f, r5 = 0.f;
            if ((unsigned)r < (unsigned)NI) {
                const float* rp = src + (size_t)r * PITCH;
                v = *(const float4*)(rp + x0);
                if (L0) {
                    l2 = (x0 >= 2) ? rp[x0 - 2] : 0.f;
                    l1 = (x0 >= 1) ? rp[x0 - 1] : 0.f;
                }
                if (L31) {
                    r4 = (x0 + 4 < NI) ? rp[x0 + 4] : 0.f;
                    r5 = (x0 + 5 < NI) ? rp[x0 + 5] : 0.f;
                }
            }
            float sl2 = __shfl_up_sync(FULL, v.z, 1);
            float sl1 = __shfl_up_sync(FULL, v.w, 1);
            float sr4 = __shfl_down_sync(FULL, v.x, 1);
            float sr5 = __shfl_down_sync(FULL, v.y, 1);
            if (!L0)  { l2 = sl2; l1 = sl1; }
            if (!L31) { r4 = sr4; r5 = sr5; }
            inC[0] = l2;  inC[1] = l1;
            inC[2] = v.x; inC[3] = v.y; inC[4] = v.z; inC[5] = v.w;
            inC[6] = r4;  inC[7] = r5;
        }

        // ---- shift mid window + force, compute mid row rm = r-1 ----
        #pragma unroll
        for (int i = 0; i < 6; i++) { mA[i] = mB[i]; mB[i] = mC[i]; }
        fA = fB;

        const int rm = r - 1;
        {
            float4 f4; f4.x = f4.y = f4.z = f4.w = 0.f;
            float fl = 0.f, fr = 0.f;
            const bool rowok = ((unsigned)rm < (unsigned)NI);
            if (rowok) {
                const float* fp = frc + (size_t)rm * PITCH;
                f4 = *(const float4*)(fp + x0);
                if (L0)  fl = (x0 >= 1)     ? fp[x0 - 1] : 0.f;
                if (L31) fr = (x0 + 4 < NI) ? fp[x0 + 4] : 0.f;
            }
            float sfl = __shfl_up_sync(FULL, f4.w, 1);
            float sfr = __shfl_down_sync(FULL, f4.x, 1);
            if (!L0)  fl = sfl;
            if (!L31) fr = sfr;
            fB = f4;

            if (rowok) {
                float f6[6];
                f6[0] = fl;   f6[1] = f4.x; f6[2] = f4.y;
                f6[3] = f4.z; f6[4] = f4.w; f6[5] = fr;
                #pragma unroll
                for (int i = 0; i < 6; i++) {
                    int gc = x0 - 1 + i;
                    float vmid = f6[i]
                        + c0 * inA[i] + c1 * inA[i + 1] + c2 * inA[i + 2]
                        + c3 * inB[i] + c4 * inB[i + 1] + c5 * inB[i + 2]
                        + c6 * inC[i] + c7 * inC[i + 1] + c8 * inC[i + 2];
                    mC[i] = ((unsigned)gc < (unsigned)NI) ? vmid : 0.f;
                }
            } else {
                #pragma unroll
                for (int i = 0; i < 6; i++) mC[i] = 0.f;
            }
        }

        // ---- output row ro = r-2 ----
        const int ro = r - 2;
        if (ro >= ybase && ro < NI) {
            float o[4];
            #pragma unroll
            for (int j = 0; j < 4; j++) {
                o[j] = c0 * mA[j] + c1 * mA[j + 1] + c2 * mA[j + 2]
                     + c3 * mB[j] + c4 * mB[j + 1] + c5 * mB[j + 2]
                     + c6 * mC[j] + c7 * mC[j + 1] + c8 * mC[j + 2];
            }
            float* orow = dst + (size_t)ro * out_pitch;
            if (!COMPACT_OUT && x0 + 3 < NI) {
                float4 ov;
                ov.x = o[0] + fA.x; ov.y = o[1] + fA.y;
                ov.z = o[2] + fA.z; ov.w = o[3] + fA.w;
                *(float4*)(orow + x0) = ov;
            } else {
                if (x0 + 0 < NI) orow[x0 + 0] = o[0] + fA.x;
                if (x0 + 1 < NI) orow[x0 + 1] = o[1] + fA.y;
                if (x0 + 2 < NI) orow[x0 + 2] = o[2] + fA.z;
                if (x0 + 3 < NI) orow[x0 + 3] = o[3] + fA.w;
            }
        }
    }
}

extern "C" void kernel_launch(void* const* d_in, const int* in_sizes, int n_in,
                              void* d_out, int out_size) {
    // metadata order: x, pre, f, mu, k1, k2, k3  (x unused by the reference)
    const float* pre = (const float*)d_in[1];
    const float* f   = (const float*)d_in[2];
    const float* mu  = (const float*)d_in[3];
    const float* k1  = (const float*)d_in[4];
    const float* k2  = (const float*)d_in[5];
    const float* k3  = (const float*)d_in[6];
    float* out = (float*)d_out;

    void *pA = nullptr, *pB = nullptr, *pC = nullptr;
    cudaGetSymbolAddress(&pA, g_bufA);
    cudaGetSymbolAddress(&pB, g_bufB);
    cudaGetSymbolAddress(&pC, g_coef);

    setup_coef_kernel<<<1, 1>>>(mu, k1, k2, k3);
    cudaMemcpyToSymbolAsync(c_coef, pC, 9 * sizeof(float), 0,
                            cudaMemcpyDeviceToDevice);

    // step 0 (single) + force precompute, fused: pre,f -> bufA, g_force
    {
        dim3 blk(32, TY, 1);
        dim3 grd(NF / 128, (NI + TY * ROWS - 1) / (TY * ROWS), BATCH);
        step0_kernel<<<grd, blk>>>(pre, f, (float*)pA);
    }

    // 5 fused double-steps: steps 1..10
    dim3 fblk(32, FTY2, 1);
    dim3 fgrd(NF / 128, (NI + FTY2 * RROWS - 1) / (FTY2 * RROWS), BATCH);

    fused2r_kernel<false><<<fgrd, fblk>>>((const float*)pA, (float*)pB, PITCH);
    fused2r_kernel<false><<<fgrd, fblk>>>((const float*)pB, (float*)pA, PITCH);
    fused2r_kernel<false><<<fgrd, fblk>>>((const float*)pA, (float*)pB, PITCH);
    fused2r_kernel<false><<<fgrd, fblk>>>((const float*)pB, (float*)pA, PITCH);
    fused2r_kernel<true ><<<fgrd, fblk>>>((const float*)pA, out, NI);
}

// round 10
// speedup vs baseline: 1.5315x; 1.2242x over previous
#include <cuda_runtime.h>

#define NI      1022      // interior size (N-2)
#define NF      1024      // full size N
#define PITCH   1056      // padded row pitch (33*128B rows)
#define XOFF    16        // field starts at col 16 -> loads at x-4 stay in-bounds
#define BATCH   8
#define ROWS    8         // output rows per thread (step-0 kernel)
#define TY      4         // thread rows per block (step-0 kernel)
#define RROWS   16        // output rows per thread (fused rolling kernel)
#define FTY2    4         // thread.y per block (fused rolling kernel)

// zero-initialized at context init; padding cols never written -> stay zero
__device__ float g_bufA[BATCH * NI * PITCH];
__device__ float g_bufB[BATCH * NI * PITCH];
__device__ float g_force[BATCH * NI * PITCH];
__device__ float g_coef[9];
__device__ float g_cf[1];

__constant__ float c_coef[9];

// --- fold mu/k1/k2/k3 into 10 scalars ---------------------------------------
__global__ void setup_coef_kernel(const float* __restrict__ mu,
                                  const float* __restrict__ k1,
                                  const float* __restrict__ k2,
                                  const float* __restrict__ k3) {
    float s3 = 0.0f;
    #pragma unroll
    for (int i = 0; i < 9; i++) s3 += k3[i];
    float inv = 1.0f / s3;
    #pragma unroll
    for (int i = 0; i < 9; i++) g_coef[i] = (k1[i] + k2[i]) * inv;
    const float Hval = 1.0f / (float)(NF - 1);
    g_cf[0] = Hval * Hval / (mu[0] * s3);
}

// --- step 0 + force precompute fused -----------------------------------------
// Reads pre (compact pitch 1022) and f (NF x NF); stores
// force = f_interior * cf into g_force (XOFF layout) and
// out = force + conv(hard_encode(pre)) -> bufA (XOFF layout).
__global__ void __launch_bounds__(32 * TY)
step0_kernel(const float* __restrict__ pre,
             const float* __restrict__ f,
             float* __restrict__ out) {
    const unsigned FULL = 0xffffffffu;
    int lane  = threadIdx.x;
    int x0    = (blockIdx.x * 32 + lane) * 4;
    int ybase = (blockIdx.y * TY + threadIdx.y) * ROWS;
    int b     = blockIdx.z;

    float c0 = c_coef[0], c1 = c_coef[1], c2 = c_coef[2];
    float c3 = c_coef[3], c4 = c_coef[4], c5 = c_coef[5];
    float c6 = c_coef[6], c7 = c_coef[7], c8 = c_coef[8];
    const float cf = g_cf[0];

    const float* src = pre + (size_t)b * NI * NI;
    const bool L31 = (lane == 31);

    float4 acc[ROWS];
    #pragma unroll
    for (int i = 0; i < ROWS; i++) {
        int row = ybase + i;
        if (row < NI) {
            const float* fp = f + ((size_t)b * NF + (row + 1)) * NF;
            float4 q = *(const float4*)(fp + x0);
            float t4 = __shfl_down_sync(FULL, q.x, 1);
            if (L31) t4 = (x0 + 4 < NF) ? fp[x0 + 4] : 0.0f;
            float4 a; a.x = q.y * cf; a.y = q.z * cf; a.z = q.w * cf; a.w = t4 * cf;
            acc[i] = a;
            float* frow = g_force + ((size_t)b * NI + row) * PITCH + XOFF;
            if (x0 + 3 < NI) {
                *(float4*)(frow + x0) = a;
            } else {
                if (x0 + 0 < NI) frow[x0 + 0] = a.x;
                if (x0 + 1 < NI) frow[x0 + 1] = a.y;
            }
        } else {
            acc[i].x = acc[i].y = acc[i].z = acc[i].w = 0.0f;
        }
    }

    #pragma unroll
    for (int rj = 0; rj <= ROWS + 1; rj++) {
        int ri  = rj - 1;
        int row = ybase + ri;
        if (row < 0 || row >= NI) continue;

        const float* rp = src + (size_t)row * NI;
        float l, rr; float4 v;
        l   = (x0 - 1 >= 0 && x0 - 1 < NI) ? rp[x0 - 1] : 0.0f;
        v.x = (x0 + 0 < NI) ? rp[x0 + 0] : 0.0f;
        v.y = (x0 + 1 < NI) ? rp[x0 + 1] : 0.0f;
        v.z = (x0 + 2 < NI) ? rp[x0 + 2] : 0.0f;
        v.w = (x0 + 3 < NI) ? rp[x0 + 3] : 0.0f;
        rr  = (x0 + 4 < NI) ? rp[x0 + 4] : 0.0f;

        if (ri + 1 >= 0 && ri + 1 < ROWS) {
            acc[ri + 1].x += c0 * l   + c1 * v.x + c2 * v.y;
            acc[ri + 1].y += c0 * v.x + c1 * v.y + c2 * v.z;
            acc[ri + 1].z += c0 * v.y + c1 * v.z + c2 * v.w;
            acc[ri + 1].w += c0 * v.z + c1 * v.w + c2 * rr;
        }
        if (ri >= 0 && ri < ROWS) {
            acc[ri].x += c3 * l   + c4 * v.x + c5 * v.y;
            acc[ri].y += c3 * v.x + c4 * v.y + c5 * v.z;
            acc[ri].z += c3 * v.y + c4 * v.z + c5 * v.w;
            acc[ri].w += c3 * v.z + c4 * v.w + c5 * rr;
        }
        if (ri - 1 >= 0 && ri - 1 < ROWS) {
            acc[ri - 1].x += c6 * l   + c7 * v.x + c8 * v.y;
            acc[ri - 1].y += c6 * v.x + c7 * v.y + c8 * v.z;
            acc[ri - 1].z += c6 * v.y + c7 * v.z + c8 * v.w;
            acc[ri - 1].w += c6 * v.z + c7 * v.w + c8 * rr;
        }
    }

    #pragma unroll
    for (int i = 0; i < ROWS; i++) {
        int row = ybase + i;
        if (row >= NI) continue;
        float* orow = out + ((size_t)b * NI + row) * PITCH + XOFF;
        if (x0 + 3 < NI) {
            *(float4*)(orow + x0) = acc[i];
        } else {
            if (x0 + 0 < NI) orow[x0 + 0] = acc[i].x;
            if (x0 + 1 < NI) orow[x0 + 1] = acc[i].y;
        }
    }
}

// --- fused 2-step Jacobi, register-rolling, shuffle-free ----------------------
// Thread owns cols [x0, x0+4) and output rows [ybase, ybase+RROWS).
// Windows assembled from 3 aligned float4 loads per row (padded XOFF layout
// provides zeros outside the domain in x; row guards handle y).
template<bool COMPACT_OUT>
__global__ void __launch_bounds__(32 * FTY2)
fused2r_kernel(const float* __restrict__ in,
               float* __restrict__ out, int out_pitch) {
    const int lane  = threadIdx.x;
    const int x0    = (blockIdx.x * 32 + lane) * 4;
    const int ybase = (blockIdx.y * FTY2 + threadIdx.y) * RROWS;
    const int b     = blockIdx.z;

    const float c0 = c_coef[0], c1 = c_coef[1], c2 = c_coef[2];
    const float c3 = c_coef[3], c4 = c_coef[4], c5 = c_coef[5];
    const float c6 = c_coef[6], c7 = c_coef[7], c8 = c_coef[8];

    const float* src = in      + (size_t)b * NI * PITCH + XOFF;
    const float* frc = g_force + (size_t)b * NI * PITCH + XOFF;
    float*       dst = out     + (size_t)b * NI * out_pitch;

    float inA[8], inB[8], inC[8];   // input rows r-2, r-1, r (cols x0-2..x0+5)
    float mA[6],  mB[6],  mC[6];    // mid rows r-3, r-2, r-1 (cols x0-1..x0+4)
    float4 fA, fB;                  // force rows r-2, r-1 (4-wide)
    float  flA, frA, flB, frB;      // force halo cols x0-1, x0+4 for those rows

    #pragma unroll
    for (int i = 0; i < 8; i++) { inA[i] = 0.f; inB[i] = 0.f; inC[i] = 0.f; }
    #pragma unroll
    for (int i = 0; i < 6; i++) { mA[i] = 0.f; mB[i] = 0.f; mC[i] = 0.f; }
    fA.x = fA.y = fA.z = fA.w = 0.f; fB = fA;
    flA = frA = flB = frB = 0.f;

    // incremental row pointers (start at row ybase-2 for src, ybase-3 for force)
    const float* rp = src + (size_t)(ybase - 2) * PITCH;
    const float* fp = frc + (size_t)(ybase - 3) * PITCH;

    for (int it = 0; it < RROWS + 4; it++) {
        const int r = ybase - 2 + it;

        // ---- shift input window, load row r (3 aligned float4, no shuffles) --
        #pragma unroll
        for (int i = 0; i < 8; i++) { inA[i] = inB[i]; inB[i] = inC[i]; }
        if ((unsigned)r < (unsigned)NI) {
            float4 qa = *(const float4*)(rp + x0 - 4);
            float4 qb = *(const float4*)(rp + x0);
            float4 qc = *(const float4*)(rp + x0 + 4);
            inC[0] = qa.z; inC[1] = qa.w;
            inC[2] = qb.x; inC[3] = qb.y; inC[4] = qb.z; inC[5] = qb.w;
            inC[6] = qc.x; inC[7] = qc.y;
        } else {
            #pragma unroll
            for (int i = 0; i < 8; i++) inC[i] = 0.f;
        }
        rp += PITCH;

        // ---- shift mid + force windows, compute mid row rm = r-1 -------------
        #pragma unroll
        for (int i = 0; i < 6; i++) { mA[i] = mB[i]; mB[i] = mC[i]; }
        fA = fB; flA = flB; frA = frB;

        const int rm = r - 1;
        if ((unsigned)rm < (unsigned)NI) {
            float4 pa = *(const float4*)(fp + x0 - 4);
            float4 pb = *(const float4*)(fp + x0);
            float4 pc = *(const float4*)(fp + x0 + 4);
            fB = pb; flB = pa.w; frB = pc.x;

            float f6[6];
            f6[0] = pa.w; f6[1] = pb.x; f6[2] = pb.y;
            f6[3] = pb.z; f6[4] = pb.w; f6[5] = pc.x;
            #pragma unroll
            for (int i = 0; i < 6; i++) {
                int gc = x0 - 1 + i;
                float vmid = f6[i]
                    + c0 * inA[i] + c1 * inA[i + 1] + c2 * inA[i + 2]
                    + c3 * inB[i] + c4 * inB[i + 1] + c5 * inB[i + 2]
                    + c6 * inC[i] + c7 * inC[i + 1] + c8 * inC[i + 2];
                mC[i] = ((unsigned)gc < (unsigned)NI) ? vmid : 0.f;
            }
        } else {
            fB.x = fB.y = fB.z = fB.w = 0.f; flB = frB = 0.f;
            #pragma unroll
            for (int i = 0; i < 6; i++) mC[i] = 0.f;
        }
        fp += PITCH;

        // ---- output row ro = r-2 ---------------------------------------------
        const int ro = r - 2;
        if (ro >= ybase && ro < NI) {
            float o[4];
            #pragma unroll
            for (int j = 0; j < 4; j++) {
                o[j] = c0 * mA[j] + c1 * mA[j + 1] + c2 * mA[j + 2]
                     + c3 * mB[j] + c4 * mB[j + 1] + c5 * mB[j + 2]
                     + c6 * mC[j] + c7 * mC[j + 1] + c8 * mC[j + 2];
            }
            if (!COMPACT_OUT) {
                float* orow = dst + (size_t)ro * out_pitch + XOFF;
                if (x0 + 3 < NI) {
                    float4 ov;
                    ov.x = o[0] + fA.x; ov.y = o[1] + fA.y;
                    ov.z = o[2] + fA.z; ov.w = o[3] + fA.w;
                    *(float4*)(orow + x0) = ov;
                } else {
                    if (x0 + 0 < NI) orow[x0 + 0] = o[0] + fA.x;
                    if (x0 + 1 < NI) orow[x0 + 1] = o[1] + fA.y;
                }
            } else {
                float* orow = dst + (size_t)ro * out_pitch;   // compact d_out
                if (x0 + 0 < NI) orow[x0 + 0] = o[0] + fA.x;
                if (x0 + 1 < NI) orow[x0 + 1] = o[1] + fA.y;
                if (x0 + 2 < NI) orow[x0 + 2] = o[2] + fA.z;
                if (x0 + 3 < NI) orow[x0 + 3] = o[3] + fA.w;
            }
        }
    }
    (void)flA; (void)frA;   // halo regs kept for symmetry; compiler prunes
}

extern "C" void kernel_launch(void* const* d_in, const int* in_sizes, int n_in,
                              void* d_out, int out_size) {
    // metadata order: x, pre, f, mu, k1, k2, k3  (x unused by the reference)
    const float* pre = (const float*)d_in[1];
    const float* f   = (const float*)d_in[2];
    const float* mu  = (const float*)d_in[3];
    const float* k1  = (const float*)d_in[4];
    const float* k2  = (const float*)d_in[5];
    const float* k3  = (const float*)d_in[6];
    float* out = (float*)d_out;

    void *pA = nullptr, *pB = nullptr, *pC = nullptr;
    cudaGetSymbolAddress(&pA, g_bufA);
    cudaGetSymbolAddress(&pB, g_bufB);
    cudaGetSymbolAddress(&pC, g_coef);

    setup_coef_kernel<<<1, 1>>>(mu, k1, k2, k3);
    cudaMemcpyToSymbolAsync(c_coef, pC, 9 * sizeof(float), 0,
                            cudaMemcpyDeviceToDevice);

    // step 0 (single) + force precompute, fused: pre,f -> bufA, g_force
    {
        dim3 blk(32, TY, 1);
        dim3 grd(NF / 128, (NI + TY * ROWS - 1) / (TY * ROWS), BATCH);
        step0_kernel<<<grd, blk>>>(pre, f, (float*)pA);
    }

    // 5 fused double-steps: steps 1..10
    dim3 fblk(32, FTY2, 1);
    dim3 fgrd(NF / 128, (NI + FTY2 * RROWS - 1) / (FTY2 * RROWS), BATCH);

    fused2r_kernel<false><<<fgrd, fblk>>>((const float*)pA, (float*)pB, PITCH);
    fused2r_kernel<false><<<fgrd, fblk>>>((const float*)pB, (float*)pA, PITCH);
    fused2r_kernel<false><<<fgrd, fblk>>>((const float*)pA, (float*)pB, PITCH);
    fused2r_kernel<false><<<fgrd, fblk>>>((const float*)pB, (float*)pA, PITCH);
    fused2r_kernel<true ><<<fgrd, fblk>>>((const float*)pA, out, NI);
}